// round 1
// baseline (speedup 1.0000x reference)
#include <cuda_runtime.h>
#include <math.h>

#define Bb 2
#define Nn 160
#define Cc 256
#define Hh 8
#define Dd 32
#define ROWS (Bb*Nn*Nn)   // 51200

// Scratch (allocation-free rule: __device__ globals)
__device__ float g_qkv[(size_t)ROWS*768];
__device__ float g_att[(size_t)ROWS*Cc];
__device__ float g_proj[(size_t)ROWS*Cc];
__device__ float g_x1[(size_t)ROWS*Cc];

// ---------------- SGEMM: C[M,Nc] = A[M,K] @ B[K,Nc], row-major, M%128==0, Nc%128==0, K%16==0
__global__ __launch_bounds__(256) void sgemm128(const float* __restrict__ A,
                                                const float* __restrict__ Bm,
                                                float* __restrict__ Cm,
                                                int K, int Nc) {
    __shared__ float As[16][128];
    __shared__ float Bs[16][128];
    const int t  = threadIdx.x;
    const int bm = blockIdx.y * 128;
    const int bn = blockIdx.x * 128;
    const int tx = t & 15;
    const int ty = t >> 4;

    float acc[8][8];
#pragma unroll
    for (int i = 0; i < 8; i++)
#pragma unroll
        for (int j = 0; j < 8; j++) acc[i][j] = 0.f;

    for (int k0 = 0; k0 < K; k0 += 16) {
#pragma unroll
        for (int rep = 0; rep < 2; rep++) {
            int idx = t + rep * 256;
            // A tile (128 rows x 16 k), store transposed As[k][m]
            int m  = idx >> 2;
            int kk = (idx & 3) << 2;
            float4 av = *reinterpret_cast<const float4*>(A + (size_t)(bm + m) * K + k0 + kk);
            As[kk + 0][m] = av.x; As[kk + 1][m] = av.y;
            As[kk + 2][m] = av.z; As[kk + 3][m] = av.w;
            // B tile (16 k x 128 cols)
            int kb = idx >> 5;
            int n4 = (idx & 31) << 2;
            *reinterpret_cast<float4*>(&Bs[kb][n4]) =
                *reinterpret_cast<const float4*>(Bm + (size_t)(k0 + kb) * Nc + bn + n4);
        }
        __syncthreads();
#pragma unroll
        for (int kk = 0; kk < 16; kk++) {
            float4 a0 = *reinterpret_cast<const float4*>(&As[kk][ty * 8]);
            float4 a1 = *reinterpret_cast<const float4*>(&As[kk][ty * 8 + 4]);
            float4 b0 = *reinterpret_cast<const float4*>(&Bs[kk][tx * 8]);
            float4 b1 = *reinterpret_cast<const float4*>(&Bs[kk][tx * 8 + 4]);
            float a[8] = {a0.x, a0.y, a0.z, a0.w, a1.x, a1.y, a1.z, a1.w};
            float b[8] = {b0.x, b0.y, b0.z, b0.w, b1.x, b1.y, b1.z, b1.w};
#pragma unroll
            for (int i = 0; i < 8; i++)
#pragma unroll
                for (int j = 0; j < 8; j++) acc[i][j] += a[i] * b[j];
        }
        __syncthreads();
    }
#pragma unroll
    for (int i = 0; i < 8; i++) {
        float* cp = Cm + (size_t)(bm + ty * 8 + i) * Nc + bn + tx * 8;
        *reinterpret_cast<float4*>(cp)     = make_float4(acc[i][0], acc[i][1], acc[i][2], acc[i][3]);
        *reinterpret_cast<float4*>(cp + 4) = make_float4(acc[i][4], acc[i][5], acc[i][6], acc[i][7]);
    }
}

// ---------------- Fused attention per (b, m, h). Online softmax, K/V in SMEM.
// bias[b,h,i,j] = map[b, i*si + j*sj] * bw[h] + bb[h]   (si/sj encode map transpose)
__global__ __launch_bounds__(Nn) void attn_kernel(const float* __restrict__ qkv,
                                                  const float* __restrict__ map,
                                                  const float* __restrict__ bw,
                                                  const float* __restrict__ bb,
                                                  float* __restrict__ out,
                                                  int si, int sj) {
    const int h = blockIdx.x;
    const int m = blockIdx.y;
    const int b = blockIdx.z;
    const int i = threadIdx.x;

    __shared__ float ks[Nn][Dd + 1];
    __shared__ float vs[Nn][Dd + 1];

    const size_t rowbase = ((size_t)b * Nn + m) * Nn;
    const float scale = 0.17677669529663687f;  // 1/sqrt(32)

    // cooperative load of K and V rows (thread i loads row i)
    {
        const float* kp = qkv + (rowbase + i) * 768 + 256 + h * Dd;
#pragma unroll
        for (int d = 0; d < Dd; d++) {
            ks[i][d] = kp[d];
            vs[i][d] = kp[256 + d];
        }
    }
    float q[Dd];
    {
        const float* qp = qkv + (rowbase + i) * 768 + h * Dd;
#pragma unroll
        for (int d = 0; d < Dd; d++) q[d] = qp[d] * scale;
    }
    __syncthreads();

    const float wv = bw[h];
    const float bv = bb[h];
    const float* mp = map + (size_t)b * Nn * Nn + (size_t)i * si;

    float mi = -INFINITY, li = 0.f;
    float acc[Dd];
#pragma unroll
    for (int d = 0; d < Dd; d++) acc[d] = 0.f;

    for (int j = 0; j < Nn; j++) {
        float s = 0.f;
#pragma unroll
        for (int d = 0; d < Dd; d++) s += q[d] * ks[j][d];
        s += mp[(size_t)j * sj] * wv + bv;

        if (s > mi) {
            float f = __expf(mi - s);   // expf(-inf)=0 on first iter
            li *= f;
#pragma unroll
            for (int d = 0; d < Dd; d++) acc[d] *= f;
            mi = s;
        }
        float p = __expf(s - mi);
        li += p;
#pragma unroll
        for (int d = 0; d < Dd; d++) acc[d] += p * vs[j][d];
    }

    const float inv = 1.f / li;
    float* op = out + (rowbase + i) * Cc + h * Dd;
#pragma unroll
    for (int d = 0; d < Dd; d++) op[d] = acc[d] * inv;
}

// ---------------- Residual + LayerNorm, writing output transposed over the two N axes.
__global__ __launch_bounds__(Cc) void ln_kernel(const float* __restrict__ xin,
                                                const float* __restrict__ proj,
                                                const float* __restrict__ g,
                                                const float* __restrict__ bt,
                                                float* __restrict__ out) {
    const int r = blockIdx.x;
    const int c = threadIdx.x;
    const float v = xin[(size_t)r * Cc + c] + proj[(size_t)r * Cc + c];

    float s = v, s2 = v * v;
#pragma unroll
    for (int o = 16; o > 0; o >>= 1) {
        s  += __shfl_down_sync(0xffffffffu, s, o);
        s2 += __shfl_down_sync(0xffffffffu, s2, o);
    }
    __shared__ float ws[8], ws2[8];
    const int w = c >> 5, l = c & 31;
    if (l == 0) { ws[w] = s; ws2[w] = s2; }
    __syncthreads();
    if (w == 0) {
        s  = (l < 8) ? ws[l]  : 0.f;
        s2 = (l < 8) ? ws2[l] : 0.f;
#pragma unroll
        for (int o = 4; o > 0; o >>= 1) {
            s  += __shfl_down_sync(0xffffffffu, s, o);
            s2 += __shfl_down_sync(0xffffffffu, s2, o);
        }
        if (l == 0) { ws[0] = s; ws2[0] = s2; }
    }
    __syncthreads();
    const float mean = ws[0] * (1.f / Cc);
    const float var  = ws2[0] * (1.f / Cc) - mean * mean;
    const float rs   = rsqrtf(var + 1e-5f);

    const int bidx = r / (Nn * Nn);
    const int rem  = r % (Nn * Nn);
    const int mm   = rem / Nn;
    const int ii   = rem % Nn;
    const size_t rt = ((size_t)bidx * Nn + ii) * Nn + mm;  // swap the two N axes
    out[rt * Cc + c] = (v - mean) * rs * g[c] + bt[c];
}

extern "C" void kernel_launch(void* const* d_in, const int* in_sizes, int n_in,
                              void* d_out, int out_size) {
    const float* pair      = (const float*)d_in[0];
    const float* bulk      = (const float*)d_in[1];
    const float* row_qkv_w = (const float*)d_in[2];
    const float* row_out_w = (const float*)d_in[3];
    const float* row_ln_g  = (const float*)d_in[4];
    const float* row_ln_b  = (const float*)d_in[5];
    const float* row_bw    = (const float*)d_in[6];
    const float* row_bb    = (const float*)d_in[7];
    const float* col_qkv_w = (const float*)d_in[8];
    const float* col_out_w = (const float*)d_in[9];
    const float* col_ln_g  = (const float*)d_in[10];
    const float* col_ln_b  = (const float*)d_in[11];
    const float* col_bw    = (const float*)d_in[12];
    const float* col_bb    = (const float*)d_in[13];
    float* out = (float*)d_out;

    float *qkv, *att, *proj, *x1;
    cudaGetSymbolAddress((void**)&qkv,  g_qkv);
    cudaGetSymbolAddress((void**)&att,  g_att);
    cudaGetSymbolAddress((void**)&proj, g_proj);
    cudaGetSymbolAddress((void**)&x1,   g_x1);

    dim3 gq(768 / 128, ROWS / 128);
    dim3 gp(256 / 128, ROWS / 128);
    dim3 ga(Hh, Nn, Bb);

    // ---- pass 1 (row attention), LN writes transposed into x1
    sgemm128<<<gq, 256>>>(pair, row_qkv_w, qkv, 256, 768);
    attn_kernel<<<ga, Nn>>>(qkv, bulk, row_bw, row_bb, att, Nn, 1);
    sgemm128<<<gp, 256>>>(att, row_out_w, proj, 256, 256);
    ln_kernel<<<ROWS, Cc>>>(pair, proj, row_ln_g, row_ln_b, x1);

    // ---- pass 2 (column attention on transposed x), LN writes transposed back into out
    sgemm128<<<gq, 256>>>(x1, col_qkv_w, qkv, 256, 768);
    attn_kernel<<<ga, Nn>>>(qkv, bulk, col_bw, col_bb, att, 1, Nn);
    sgemm128<<<gp, 256>>>(att, col_out_w, proj, 256, 256);
    ln_kernel<<<ROWS, Cc>>>(x1, proj, col_ln_g, col_ln_b, out);
}

// round 4
// speedup vs baseline: 1.2333x; 1.2333x over previous
#include <cuda_runtime.h>
#include <cuda_bf16.h>
#include <math.h>
#include <cstdint>

#define Bb 2
#define Nn 160
#define Cc 256
#define Hh 8
#define Dd 32
#define ROWS (Bb*Nn*Nn)   // 51200
#define GK 256            // inner K of all GEMMs

// ---------------- scratch (__device__ globals; no allocation allowed) ----------------
__device__ float g_qkv[(size_t)ROWS*768];
__device__ float g_att[(size_t)ROWS*Cc];
__device__ float g_proj[(size_t)ROWS*Cc];
__device__ float g_x1[(size_t)ROWS*Cc];
__device__ __nv_bfloat16 g_Ah[(size_t)ROWS*GK];
__device__ __nv_bfloat16 g_Al[(size_t)ROWS*GK];
__device__ __nv_bfloat16 g_Bt[(size_t)768*2*GK];   // [Nc, 2K]: cols [0,K)=hi, [K,2K)=lo

__device__ __forceinline__ uint32_t smem_u32(const void* p) {
    uint32_t a;
    asm("{ .reg .u64 t; cvta.to.shared.u64 t, %1; cvt.u32.u64 %0, t; }" : "=r"(a) : "l"(p));
    return a;
}
#define CP16(d, s) asm volatile("cp.async.cg.shared.global [%0], [%1], 16;" :: "r"(d), "l"(s))
#define CP_COMMIT  asm volatile("cp.async.commit_group;" ::: "memory")

// ---------------- split kernels: fp32 -> bf16 hi/lo ----------------
__global__ __launch_bounds__(256) void splitA(const float4* __restrict__ X,
                                              __nv_bfloat16* __restrict__ Ah,
                                              __nv_bfloat16* __restrict__ Al, int n4) {
    int i = blockIdx.x * blockDim.x + threadIdx.x;
    if (i >= n4) return;
    float4 x = X[i];
    __nv_bfloat16 h0 = __float2bfloat16(x.x), h1 = __float2bfloat16(x.y);
    __nv_bfloat16 h2 = __float2bfloat16(x.z), h3 = __float2bfloat16(x.w);
    __nv_bfloat16 l0 = __float2bfloat16(x.x - __bfloat162float(h0));
    __nv_bfloat16 l1 = __float2bfloat16(x.y - __bfloat162float(h1));
    __nv_bfloat16 l2 = __float2bfloat16(x.z - __bfloat162float(h2));
    __nv_bfloat16 l3 = __float2bfloat16(x.w - __bfloat162float(h3));
    reinterpret_cast<__nv_bfloat162*>(Ah)[i * 2 + 0] = __nv_bfloat162(h0, h1);
    reinterpret_cast<__nv_bfloat162*>(Ah)[i * 2 + 1] = __nv_bfloat162(h2, h3);
    reinterpret_cast<__nv_bfloat162*>(Al)[i * 2 + 0] = __nv_bfloat162(l0, l1);
    reinterpret_cast<__nv_bfloat162*>(Al)[i * 2 + 1] = __nv_bfloat162(l2, l3);
}

// W [K, Nc] row-major -> Bt [Nc, 2K]: Bt[n, k] = hi(W[k,n]), Bt[n, K+k] = lo(W[k,n])
__global__ __launch_bounds__(256) void splitB(const float* __restrict__ W,
                                              __nv_bfloat16* __restrict__ Bt, int Nc) {
    int idx = blockIdx.x * blockDim.x + threadIdx.x;
    if (idx >= GK * Nc) return;
    int k = idx / Nc, n = idx % Nc;
    float x = W[idx];
    __nv_bfloat16 h = __float2bfloat16(x);
    Bt[(size_t)n * (2 * GK) + k]      = h;
    Bt[(size_t)n * (2 * GK) + GK + k] = __float2bfloat16(x - __bfloat162float(h));
}

// ---------------- bf16 mma.sync GEMM: C[M,Nc] = A @ W (fp32 via 3-split) ----------------
// BM=128, BN=128, BK=32, 256 thr (8 warps 4x2), warp tile 32x64, 2-stage cp.async.
#define SSTR 40   // smem row stride in bf16 elems (80B: 16B-aligned, ldmatrix conflict-free)

__global__ __launch_bounds__(256) void gemm_mma(const __nv_bfloat16* __restrict__ Ah,
                                                const __nv_bfloat16* __restrict__ Al,
                                                const __nv_bfloat16* __restrict__ Bt,
                                                float* __restrict__ C, int Nc) {
    __shared__ __align__(16) __nv_bfloat16 As[2][128 * SSTR];
    __shared__ __align__(16) __nv_bfloat16 Bs[2][128 * SSTR];

    const int tid = threadIdx.x;
    const int wid = tid >> 5, l = tid & 31;
    const int wm = (wid & 3) * 32;       // warp row offset in tile
    const int wn = (wid >> 2) * 64;      // warp col offset in tile
    const int bm = blockIdx.y * 128, bn = blockIdx.x * 128;

    float acc[2][8][4];
#pragma unroll
    for (int mt = 0; mt < 2; mt++)
#pragma unroll
        for (int nt = 0; nt < 8; nt++)
#pragma unroll
            for (int r = 0; r < 4; r++) acc[mt][nt][r] = 0.f;

    // global->smem async load of chunk c into stage st
    auto load_chunk = [&](int c, int st) {
        const int blk = c >> 3;                 // 0: Ah*Bh  1: Ah*Bl  2: Al*Bh
        const int k0 = (c & 7) * 32;
        const __nv_bfloat16* Ap = (blk < 2 ? Ah : Al);
        const __nv_bfloat16* Bp = Bt + (blk == 1 ? GK : 0);
#pragma unroll
        for (int w = 0; w < 2; w++) {
            int idx = tid + w * 256;
            int row = idx >> 2, seg = (idx & 3) * 8;
            CP16(smem_u32(&As[st][row * SSTR + seg]),
                 Ap + (size_t)(bm + row) * GK + k0 + seg);
            CP16(smem_u32(&Bs[st][row * SSTR + seg]),
                 Bp + (size_t)(bn + row) * (2 * GK) + k0 + seg);
        }
        CP_COMMIT;
    };

    load_chunk(0, 0);

    for (int c = 0; c < 24; c++) {
        const int st = c & 1;
        if (c + 1 < 24) {
            load_chunk(c + 1, st ^ 1);
            asm volatile("cp.async.wait_group 1;" ::: "memory");
        } else {
            asm volatile("cp.async.wait_group 0;" ::: "memory");
        }
        __syncthreads();

        const uint32_t aBase = smem_u32(&As[st][0]);
        const uint32_t bBase = smem_u32(&Bs[st][0]);
#pragma unroll
        for (int ks = 0; ks < 32; ks += 16) {
            uint32_t a[2][4];
#pragma unroll
            for (int mt = 0; mt < 2; mt++) {
                uint32_t addr = aBase +
                    (((wm + mt * 16 + (l & 15)) * SSTR) + ks + ((l >> 4) << 3)) * 2;
                asm volatile("ldmatrix.sync.aligned.m8n8.x4.shared.b16 {%0,%1,%2,%3}, [%4];"
                             : "=r"(a[mt][0]), "=r"(a[mt][1]), "=r"(a[mt][2]), "=r"(a[mt][3])
                             : "r"(addr));
            }
            uint32_t b[8][2];
#pragma unroll
            for (int p = 0; p < 4; p++) {
                uint32_t addr = bBase +
                    (((wn + p * 16 + (l & 7) + ((l >> 4) << 3)) * SSTR) +
                     ks + (((l >> 3) & 1) << 3)) * 2;
                asm volatile("ldmatrix.sync.aligned.m8n8.x4.shared.b16 {%0,%1,%2,%3}, [%4];"
                             : "=r"(b[p * 2][0]), "=r"(b[p * 2][1]),
                               "=r"(b[p * 2 + 1][0]), "=r"(b[p * 2 + 1][1])
                             : "r"(addr));
            }
#pragma unroll
            for (int mt = 0; mt < 2; mt++)
#pragma unroll
                for (int nt = 0; nt < 8; nt++)
                    asm volatile(
                        "mma.sync.aligned.m16n8k16.row.col.f32.bf16.bf16.f32 "
                        "{%0,%1,%2,%3}, {%4,%5,%6,%7}, {%8,%9}, {%0,%1,%2,%3};"
                        : "+f"(acc[mt][nt][0]), "+f"(acc[mt][nt][1]),
                          "+f"(acc[mt][nt][2]), "+f"(acc[mt][nt][3])
                        : "r"(a[mt][0]), "r"(a[mt][1]), "r"(a[mt][2]), "r"(a[mt][3]),
                          "r"(b[nt][0]), "r"(b[nt][1]));
        }
        __syncthreads();
    }

    // epilogue: fp32 accum -> C
#pragma unroll
    for (int mt = 0; mt < 2; mt++) {
        const int row = bm + wm + mt * 16 + (l >> 2);
#pragma unroll
        for (int nt = 0; nt < 8; nt++) {
            const int col = bn + wn + nt * 8 + (l & 3) * 2;
            *reinterpret_cast<float2*>(C + (size_t)row * Nc + col) =
                make_float2(acc[mt][nt][0], acc[mt][nt][1]);
            *reinterpret_cast<float2*>(C + (size_t)(row + 8) * Nc + col) =
                make_float2(acc[mt][nt][2], acc[mt][nt][3]);
        }
    }
}

// ---------------- Fused attention per (b, m, h). Online softmax, K/V in SMEM. ----------------
__global__ __launch_bounds__(Nn) void attn_kernel(const float* __restrict__ qkv,
                                                  const float* __restrict__ map,
                                                  const float* __restrict__ bw,
                                                  const float* __restrict__ bb,
                                                  float* __restrict__ out,
                                                  int si, int sj) {
    const int h = blockIdx.x;
    const int m = blockIdx.y;
    const int b = blockIdx.z;
    const int i = threadIdx.x;

    __shared__ float ks[Nn][Dd + 1];
    __shared__ float vs[Nn][Dd + 1];

    const size_t rowbase = ((size_t)b * Nn + m) * Nn;
    const float scale = 0.17677669529663687f;

    {
        const float* kp = qkv + (rowbase + i) * 768 + 256 + h * Dd;
#pragma unroll
        for (int d = 0; d < Dd; d++) {
            ks[i][d] = kp[d];
            vs[i][d] = kp[256 + d];
        }
    }
    float q[Dd];
    {
        const float* qp = qkv + (rowbase + i) * 768 + h * Dd;
#pragma unroll
        for (int d = 0; d < Dd; d++) q[d] = qp[d] * scale;
    }
    __syncthreads();

    const float wv = bw[h];
    const float bv = bb[h];
    const float* mp = map + (size_t)b * Nn * Nn + (size_t)i * si;

    float mi = -INFINITY, li = 0.f;
    float acc[Dd];
#pragma unroll
    for (int d = 0; d < Dd; d++) acc[d] = 0.f;

    for (int j = 0; j < Nn; j++) {
        float s = 0.f;
#pragma unroll
        for (int d = 0; d < Dd; d++) s += q[d] * ks[j][d];
        s += mp[(size_t)j * sj] * wv + bv;

        if (s > mi) {
            float f = __expf(mi - s);
            li *= f;
#pragma unroll
            for (int d = 0; d < Dd; d++) acc[d] *= f;
            mi = s;
        }
        float p = __expf(s - mi);
        li += p;
#pragma unroll
        for (int d = 0; d < Dd; d++) acc[d] += p * vs[j][d];
    }

    const float inv = 1.f / li;
    float* op = out + (rowbase + i) * Cc + h * Dd;
#pragma unroll
    for (int d = 0; d < Dd; d++) op[d] = acc[d] * inv;
}

// ---------------- Residual + LayerNorm, writes transposed over the two N axes ----------------
__global__ __launch_bounds__(Cc) void ln_kernel(const float* __restrict__ xin,
                                                const float* __restrict__ proj,
                                                const float* __restrict__ g,
                                                const float* __restrict__ bt,
                                                float* __restrict__ out) {
    const int r = blockIdx.x;
    const int c = threadIdx.x;
    const float v = xin[(size_t)r * Cc + c] + proj[(size_t)r * Cc + c];

    float s = v, s2 = v * v;
#pragma unroll
    for (int o = 16; o > 0; o >>= 1) {
        s  += __shfl_down_sync(0xffffffffu, s, o);
        s2 += __shfl_down_sync(0xffffffffu, s2, o);
    }
    __shared__ float ws[8], ws2[8];
    const int w = c >> 5, l = c & 31;
    if (l == 0) { ws[w] = s; ws2[w] = s2; }
    __syncthreads();
    if (w == 0) {
        s  = (l < 8) ? ws[l]  : 0.f;
        s2 = (l < 8) ? ws2[l] : 0.f;
#pragma unroll
        for (int o = 4; o > 0; o >>= 1) {
            s  += __shfl_down_sync(0xffffffffu, s, o);
            s2 += __shfl_down_sync(0xffffffffu, s2, o);
        }
        if (l == 0) { ws[0] = s; ws2[0] = s2; }
    }
    __syncthreads();
    const float mean = ws[0] * (1.f / Cc);
    const float var  = ws2[0] * (1.f / Cc) - mean * mean;
    const float rs   = rsqrtf(var + 1e-5f);

    const int bidx = r / (Nn * Nn);
    const int rem  = r % (Nn * Nn);
    const int mm   = rem / Nn;
    const int ii   = rem % Nn;
    const size_t rt = ((size_t)bidx * Nn + ii) * Nn + mm;
    out[rt * Cc + c] = (v - mean) * rs * g[c] + bt[c];
}

extern "C" void kernel_launch(void* const* d_in, const int* in_sizes, int n_in,
                              void* d_out, int out_size) {
    const float* pair      = (const float*)d_in[0];
    const float* bulk      = (const float*)d_in[1];
    const float* row_qkv_w = (const float*)d_in[2];
    const float* row_out_w = (const float*)d_in[3];
    const float* row_ln_g  = (const float*)d_in[4];
    const float* row_ln_b  = (const float*)d_in[5];
    const float* row_bw    = (const float*)d_in[6];
    const float* row_bb    = (const float*)d_in[7];
    const float* col_qkv_w = (const float*)d_in[8];
    const float* col_out_w = (const float*)d_in[9];
    const float* col_ln_g  = (const float*)d_in[10];
    const float* col_ln_b  = (const float*)d_in[11];
    const float* col_bw    = (const float*)d_in[12];
    const float* col_bb    = (const float*)d_in[13];
    float* out = (float*)d_out;

    float *qkv, *att, *proj, *x1;
    __nv_bfloat16 *Ah, *Al, *Bt;
    cudaGetSymbolAddress((void**)&qkv,  g_qkv);
    cudaGetSymbolAddress((void**)&att,  g_att);
    cudaGetSymbolAddress((void**)&proj, g_proj);
    cudaGetSymbolAddress((void**)&x1,   g_x1);
    cudaGetSymbolAddress((void**)&Ah,   g_Ah);
    cudaGetSymbolAddress((void**)&Al,   g_Al);
    cudaGetSymbolAddress((void**)&Bt,   g_Bt);

    const int n4 = ROWS * GK / 4;
    const int gsplitA = (n4 + 255) / 256;
    dim3 gq(768 / 128, ROWS / 128);
    dim3 gp(256 / 128, ROWS / 128);
    dim3 ga(Hh, Nn, Bb);

    // ---- pass 1 (row attention) ----
    splitB<<<(GK * 768 + 255) / 256, 256>>>(row_qkv_w, Bt, 768);
    splitA<<<gsplitA, 256>>>((const float4*)pair, Ah, Al, n4);
    gemm_mma<<<gq, 256>>>(Ah, Al, Bt, qkv, 768);
    attn_kernel<<<ga, Nn>>>(qkv, bulk, row_bw, row_bb, att, Nn, 1);
    splitB<<<(GK * 256 + 255) / 256, 256>>>(row_out_w, Bt, 256);
    splitA<<<gsplitA, 256>>>((const float4*)att, Ah, Al, n4);
    gemm_mma<<<gp, 256>>>(Ah, Al, Bt, proj, 256);
    ln_kernel<<<ROWS, Cc>>>(pair, proj, row_ln_g, row_ln_b, x1);

    // ---- pass 2 (column attention on transposed x) ----
    splitB<<<(GK * 768 + 255) / 256, 256>>>(col_qkv_w, Bt, 768);
    splitA<<<gsplitA, 256>>>((const float4*)x1, Ah, Al, n4);
    gemm_mma<<<gq, 256>>>(Ah, Al, Bt, qkv, 768);
    attn_kernel<<<ga, Nn>>>(qkv, bulk, col_bw, col_bb, att, 1, Nn);
    splitB<<<(GK * 256 + 255) / 256, 256>>>(col_out_w, Bt, 256);
    splitA<<<gsplitA, 256>>>((const float4*)att, Ah, Al, n4);
    gemm_mma<<<gp, 256>>>(Ah, Al, Bt, proj, 256);
    ln_kernel<<<ROWS, Cc>>>(x1, proj, col_ln_g, col_ln_b, out);
}

// round 5
// speedup vs baseline: 1.7078x; 1.3847x over previous
#include <cuda_runtime.h>
#include <cuda_bf16.h>
#include <math.h>
#include <cstdint>

#define Bb 2
#define Nn 160
#define Cc 256
#define Hh 8
#define Dd 32
#define ROWS (Bb*Nn*Nn)   // 51200
#define GK 256            // inner K of all GEMMs

// ---------------- scratch (__device__ globals; no allocation allowed) ----------------
__device__ float g_qkv[(size_t)ROWS*768];
__device__ float g_proj[(size_t)ROWS*Cc];
__device__ float g_x1[(size_t)ROWS*Cc];
__device__ __nv_bfloat16 g_Ah[(size_t)ROWS*GK];
__device__ __nv_bfloat16 g_Al[(size_t)ROWS*GK];
__device__ __nv_bfloat16 g_Bt[(size_t)768*2*GK];   // [Nc, 2K]: cols [0,K)=hi, [K,2K)=lo

__device__ __forceinline__ uint32_t smem_u32(const void* p) {
    uint32_t a;
    asm("{ .reg .u64 t; cvta.to.shared.u64 t, %1; cvt.u32.u64 %0, t; }" : "=r"(a) : "l"(p));
    return a;
}
#define CP16(d, s) asm volatile("cp.async.cg.shared.global [%0], [%1], 16;" :: "r"(d), "l"(s))
#define CP_COMMIT  asm volatile("cp.async.commit_group;" ::: "memory")

__device__ __forceinline__ uint32_t bpack(__nv_bfloat16 a, __nv_bfloat16 b) {
    __nv_bfloat162 t(a, b);
    return *reinterpret_cast<uint32_t*>(&t);
}

// ---------------- split kernels: fp32 -> bf16 hi/lo ----------------
__global__ __launch_bounds__(256) void splitA(const float4* __restrict__ X,
                                              __nv_bfloat16* __restrict__ Ah,
                                              __nv_bfloat16* __restrict__ Al, int n4) {
    int i = blockIdx.x * blockDim.x + threadIdx.x;
    if (i >= n4) return;
    float4 x = X[i];
    __nv_bfloat16 h0 = __float2bfloat16(x.x), h1 = __float2bfloat16(x.y);
    __nv_bfloat16 h2 = __float2bfloat16(x.z), h3 = __float2bfloat16(x.w);
    __nv_bfloat16 l0 = __float2bfloat16(x.x - __bfloat162float(h0));
    __nv_bfloat16 l1 = __float2bfloat16(x.y - __bfloat162float(h1));
    __nv_bfloat16 l2 = __float2bfloat16(x.z - __bfloat162float(h2));
    __nv_bfloat16 l3 = __float2bfloat16(x.w - __bfloat162float(h3));
    reinterpret_cast<__nv_bfloat162*>(Ah)[i * 2 + 0] = __nv_bfloat162(h0, h1);
    reinterpret_cast<__nv_bfloat162*>(Ah)[i * 2 + 1] = __nv_bfloat162(h2, h3);
    reinterpret_cast<__nv_bfloat162*>(Al)[i * 2 + 0] = __nv_bfloat162(l0, l1);
    reinterpret_cast<__nv_bfloat162*>(Al)[i * 2 + 1] = __nv_bfloat162(l2, l3);
}

// W [K, Nc] row-major -> Bt [Nc, 2K]: Bt[n, k] = hi(W[k,n]), Bt[n, K+k] = lo(W[k,n])
__global__ __launch_bounds__(256) void splitB(const float* __restrict__ W,
                                              __nv_bfloat16* __restrict__ Bt, int Nc) {
    int idx = blockIdx.x * blockDim.x + threadIdx.x;
    if (idx >= GK * Nc) return;
    int k = idx / Nc, n = idx % Nc;
    float x = W[idx];
    __nv_bfloat16 h = __float2bfloat16(x);
    Bt[(size_t)n * (2 * GK) + k]      = h;
    Bt[(size_t)n * (2 * GK) + GK + k] = __float2bfloat16(x - __bfloat162float(h));
}

// ---------------- bf16 mma.sync GEMM: C[M,Nc] = A @ W (fp32 via 3-split) ----------------
#define SSTR 40   // smem row stride in bf16 elems

__global__ __launch_bounds__(256) void gemm_mma(const __nv_bfloat16* __restrict__ Ah,
                                                const __nv_bfloat16* __restrict__ Al,
                                                const __nv_bfloat16* __restrict__ Bt,
                                                float* __restrict__ C, int Nc) {
    __shared__ __align__(16) __nv_bfloat16 As[2][128 * SSTR];
    __shared__ __align__(16) __nv_bfloat16 Bs[2][128 * SSTR];

    const int tid = threadIdx.x;
    const int wid = tid >> 5, l = tid & 31;
    const int wm = (wid & 3) * 32;
    const int wn = (wid >> 2) * 64;
    const int bm = blockIdx.y * 128, bn = blockIdx.x * 128;

    float acc[2][8][4];
#pragma unroll
    for (int mt = 0; mt < 2; mt++)
#pragma unroll
        for (int nt = 0; nt < 8; nt++)
#pragma unroll
            for (int r = 0; r < 4; r++) acc[mt][nt][r] = 0.f;

    auto load_chunk = [&](int c, int st) {
        const int blk = c >> 3;                 // 0: Ah*Bh  1: Ah*Bl  2: Al*Bh
        const int k0 = (c & 7) * 32;
        const __nv_bfloat16* Ap = (blk < 2 ? Ah : Al);
        const __nv_bfloat16* Bp = Bt + (blk == 1 ? GK : 0);
#pragma unroll
        for (int w = 0; w < 2; w++) {
            int idx = tid + w * 256;
            int row = idx >> 2, seg = (idx & 3) * 8;
            CP16(smem_u32(&As[st][row * SSTR + seg]),
                 Ap + (size_t)(bm + row) * GK + k0 + seg);
            CP16(smem_u32(&Bs[st][row * SSTR + seg]),
                 Bp + (size_t)(bn + row) * (2 * GK) + k0 + seg);
        }
        CP_COMMIT;
    };

    load_chunk(0, 0);

    for (int c = 0; c < 24; c++) {
        const int st = c & 1;
        if (c + 1 < 24) {
            load_chunk(c + 1, st ^ 1);
            asm volatile("cp.async.wait_group 1;" ::: "memory");
        } else {
            asm volatile("cp.async.wait_group 0;" ::: "memory");
        }
        __syncthreads();

        const uint32_t aBase = smem_u32(&As[st][0]);
        const uint32_t bBase = smem_u32(&Bs[st][0]);
#pragma unroll
        for (int ks = 0; ks < 32; ks += 16) {
            uint32_t a[2][4];
#pragma unroll
            for (int mt = 0; mt < 2; mt++) {
                uint32_t addr = aBase +
                    (((wm + mt * 16 + (l & 15)) * SSTR) + ks + ((l >> 4) << 3)) * 2;
                asm volatile("ldmatrix.sync.aligned.m8n8.x4.shared.b16 {%0,%1,%2,%3}, [%4];"
                             : "=r"(a[mt][0]), "=r"(a[mt][1]), "=r"(a[mt][2]), "=r"(a[mt][3])
                             : "r"(addr));
            }
            uint32_t b[8][2];
#pragma unroll
            for (int p = 0; p < 4; p++) {
                uint32_t addr = bBase +
                    (((wn + p * 16 + (l & 7) + ((l >> 4) << 3)) * SSTR) +
                     ks + (((l >> 3) & 1) << 3)) * 2;
                asm volatile("ldmatrix.sync.aligned.m8n8.x4.shared.b16 {%0,%1,%2,%3}, [%4];"
                             : "=r"(b[p * 2][0]), "=r"(b[p * 2][1]),
                               "=r"(b[p * 2 + 1][0]), "=r"(b[p * 2 + 1][1])
                             : "r"(addr));
            }
#pragma unroll
            for (int mt = 0; mt < 2; mt++)
#pragma unroll
                for (int nt = 0; nt < 8; nt++)
                    asm volatile(
                        "mma.sync.aligned.m16n8k16.row.col.f32.bf16.bf16.f32 "
                        "{%0,%1,%2,%3}, {%4,%5,%6,%7}, {%8,%9}, {%0,%1,%2,%3};"
                        : "+f"(acc[mt][nt][0]), "+f"(acc[mt][nt][1]),
                          "+f"(acc[mt][nt][2]), "+f"(acc[mt][nt][3])
                        : "r"(a[mt][0]), "r"(a[mt][1]), "r"(a[mt][2]), "r"(a[mt][3]),
                          "r"(b[nt][0]), "r"(b[nt][1]));
        }
        __syncthreads();
    }

#pragma unroll
    for (int mt = 0; mt < 2; mt++) {
        const int row = bm + wm + mt * 16 + (l >> 2);
#pragma unroll
        for (int nt = 0; nt < 8; nt++) {
            const int col = bn + wn + nt * 8 + (l & 3) * 2;
            *reinterpret_cast<float2*>(C + (size_t)row * Nc + col) =
                make_float2(acc[mt][nt][0], acc[mt][nt][1]);
            *reinterpret_cast<float2*>(C + (size_t)(row + 8) * Nc + col) =
                make_float2(acc[mt][nt][2], acc[mt][nt][3]);
        }
    }
}

// ---------------- Fused attention per (b, m, h): float4 everywhere, writes bf16 hi/lo ----------------
__global__ __launch_bounds__(Nn) void attn_kernel(const float* __restrict__ qkv,
                                                  const float* __restrict__ map,
                                                  const float* __restrict__ bw,
                                                  const float* __restrict__ bb,
                                                  __nv_bfloat16* __restrict__ Ah,
                                                  __nv_bfloat16* __restrict__ Al,
                                                  int si, int sj) {
    const int h = blockIdx.x;
    const int m = blockIdx.y;
    const int b = blockIdx.z;
    const int i = threadIdx.x;

    __shared__ float4 ks[Nn][9];   // 8 used + 1 pad (store-phase bank spread)
    __shared__ float4 vs[Nn][9];

    const size_t rowbase = ((size_t)b * Nn + m) * Nn;
    const float scale = 0.17677669529663687f;

    const float4* qp = reinterpret_cast<const float4*>(qkv + (rowbase + i) * 768 + h * Dd);
    const float4* kp = reinterpret_cast<const float4*>(qkv + (rowbase + i) * 768 + 256 + h * Dd);
    const float4* vp = reinterpret_cast<const float4*>(qkv + (rowbase + i) * 768 + 512 + h * Dd);

    float4 q4[8];
#pragma unroll
    for (int c = 0; c < 8; c++) {
        ks[i][c] = kp[c];
        vs[i][c] = vp[c];
        float4 t = qp[c];
        t.x *= scale; t.y *= scale; t.z *= scale; t.w *= scale;
        q4[c] = t;
    }
    __syncthreads();

    const float wv = bw[h];
    const float bv = bb[h];
    const float* mp = map + (size_t)b * Nn * Nn + (size_t)i * si;

    float mi = -INFINITY, li = 0.f;
    float4 acc4[8];
#pragma unroll
    for (int c = 0; c < 8; c++) acc4[c] = make_float4(0.f, 0.f, 0.f, 0.f);

    for (int j = 0; j < Nn; j++) {
        float s = 0.f;
#pragma unroll
        for (int c = 0; c < 8; c++) {
            float4 kk = ks[j][c];
            s += q4[c].x * kk.x + q4[c].y * kk.y + q4[c].z * kk.z + q4[c].w * kk.w;
        }
        s += mp[(size_t)j * sj] * wv + bv;

        if (s > mi) {
            float f = __expf(mi - s);
            li *= f;
#pragma unroll
            for (int c = 0; c < 8; c++) {
                acc4[c].x *= f; acc4[c].y *= f; acc4[c].z *= f; acc4[c].w *= f;
            }
            mi = s;
        }
        float p = __expf(s - mi);
        li += p;
#pragma unroll
        for (int c = 0; c < 8; c++) {
            float4 vv = vs[j][c];
            acc4[c].x += p * vv.x; acc4[c].y += p * vv.y;
            acc4[c].z += p * vv.z; acc4[c].w += p * vv.w;
        }
    }

    const float inv = 1.f / li;
    uint32_t wh[16], wl[16];
#pragma unroll
    for (int c = 0; c < 8; c++) {
        float o0 = acc4[c].x * inv, o1 = acc4[c].y * inv;
        float o2 = acc4[c].z * inv, o3 = acc4[c].w * inv;
        __nv_bfloat16 h0 = __float2bfloat16(o0), h1 = __float2bfloat16(o1);
        __nv_bfloat16 h2 = __float2bfloat16(o2), h3 = __float2bfloat16(o3);
        wh[c * 2 + 0] = bpack(h0, h1);
        wh[c * 2 + 1] = bpack(h2, h3);
        wl[c * 2 + 0] = bpack(__float2bfloat16(o0 - __bfloat162float(h0)),
                              __float2bfloat16(o1 - __bfloat162float(h1)));
        wl[c * 2 + 1] = bpack(__float2bfloat16(o2 - __bfloat162float(h2)),
                              __float2bfloat16(o3 - __bfloat162float(h3)));
    }
    uint4* ahp = reinterpret_cast<uint4*>(Ah + (rowbase + i) * GK + h * Dd);
    uint4* alp = reinterpret_cast<uint4*>(Al + (rowbase + i) * GK + h * Dd);
#pragma unroll
    for (int c = 0; c < 4; c++) {
        ahp[c] = make_uint4(wh[c * 4], wh[c * 4 + 1], wh[c * 4 + 2], wh[c * 4 + 3]);
        alp[c] = make_uint4(wl[c * 4], wl[c * 4 + 1], wl[c * 4 + 2], wl[c * 4 + 3]);
    }
}

// ---------------- Residual + LayerNorm; transposed write; optional bf16 hi/lo emit ----------------
__global__ __launch_bounds__(Cc) void ln_kernel(const float* __restrict__ xin,
                                                const float* __restrict__ proj,
                                                const float* __restrict__ g,
                                                const float* __restrict__ bt,
                                                float* __restrict__ out,
                                                __nv_bfloat16* __restrict__ Ah,
                                                __nv_bfloat16* __restrict__ Al) {
    const int r = blockIdx.x;
    const int c = threadIdx.x;
    const float v = xin[(size_t)r * Cc + c] + proj[(size_t)r * Cc + c];

    float s = v, s2 = v * v;
#pragma unroll
    for (int o = 16; o > 0; o >>= 1) {
        s  += __shfl_down_sync(0xffffffffu, s, o);
        s2 += __shfl_down_sync(0xffffffffu, s2, o);
    }
    __shared__ float ws[8], ws2[8];
    const int w = c >> 5, l = c & 31;
    if (l == 0) { ws[w] = s; ws2[w] = s2; }
    __syncthreads();
    if (w == 0) {
        s  = (l < 8) ? ws[l]  : 0.f;
        s2 = (l < 8) ? ws2[l] : 0.f;
#pragma unroll
        for (int o = 4; o > 0; o >>= 1) {
            s  += __shfl_down_sync(0xffffffffu, s, o);
            s2 += __shfl_down_sync(0xffffffffu, s2, o);
        }
        if (l == 0) { ws[0] = s; ws2[0] = s2; }
    }
    __syncthreads();
    const float mean = ws[0] * (1.f / Cc);
    const float var  = ws2[0] * (1.f / Cc) - mean * mean;
    const float rs   = rsqrtf(var + 1e-5f);

    const int bidx = r / (Nn * Nn);
    const int rem  = r % (Nn * Nn);
    const int mm   = rem / Nn;
    const int ii   = rem % Nn;
    const size_t rt = ((size_t)bidx * Nn + ii) * Nn + mm;
    const float y = (v - mean) * rs * g[c] + bt[c];
    out[rt * Cc + c] = y;
    if (Ah) {
        __nv_bfloat16 hh = __float2bfloat16(y);
        Ah[rt * GK + c] = hh;
        Al[rt * GK + c] = __float2bfloat16(y - __bfloat162float(hh));
    }
}

extern "C" void kernel_launch(void* const* d_in, const int* in_sizes, int n_in,
                              void* d_out, int out_size) {
    const float* pair      = (const float*)d_in[0];
    const float* bulk      = (const float*)d_in[1];
    const float* row_qkv_w = (const float*)d_in[2];
    const float* row_out_w = (const float*)d_in[3];
    const float* row_ln_g  = (const float*)d_in[4];
    const float* row_ln_b  = (const float*)d_in[5];
    const float* row_bw    = (const float*)d_in[6];
    const float* row_bb    = (const float*)d_in[7];
    const float* col_qkv_w = (const float*)d_in[8];
    const float* col_out_w = (const float*)d_in[9];
    const float* col_ln_g  = (const float*)d_in[10];
    const float* col_ln_b  = (const float*)d_in[11];
    const float* col_bw    = (const float*)d_in[12];
    const float* col_bb    = (const float*)d_in[13];
    float* out = (float*)d_out;

    float *qkv, *proj, *x1;
    __nv_bfloat16 *Ah, *Al, *Bt;
    cudaGetSymbolAddress((void**)&qkv,  g_qkv);
    cudaGetSymbolAddress((void**)&proj, g_proj);
    cudaGetSymbolAddress((void**)&x1,   g_x1);
    cudaGetSymbolAddress((void**)&Ah,   g_Ah);
    cudaGetSymbolAddress((void**)&Al,   g_Al);
    cudaGetSymbolAddress((void**)&Bt,   g_Bt);

    const int n4 = ROWS * GK / 4;
    const int gsplitA = (n4 + 255) / 256;
    dim3 gq(768 / 128, ROWS / 128);
    dim3 gp(256 / 128, ROWS / 128);
    dim3 ga(Hh, Nn, Bb);

    // ---- pass 1 (row attention) ----
    splitB<<<(GK * 768 + 255) / 256, 256>>>(row_qkv_w, Bt, 768);
    splitA<<<gsplitA, 256>>>((const float4*)pair, Ah, Al, n4);
    gemm_mma<<<gq, 256>>>(Ah, Al, Bt, qkv, 768);
    attn_kernel<<<ga, Nn>>>(qkv, bulk, row_bw, row_bb, Ah, Al, Nn, 1);
    splitB<<<(GK * 256 + 255) / 256, 256>>>(row_out_w, Bt, 256);
    gemm_mma<<<gp, 256>>>(Ah, Al, Bt, proj, 256);
    ln_kernel<<<ROWS, Cc>>>(pair, proj, row_ln_g, row_ln_b, x1, Ah, Al);

    // ---- pass 2 (column attention on transposed x) ----
    splitB<<<(GK * 768 + 255) / 256, 256>>>(col_qkv_w, Bt, 768);
    gemm_mma<<<gq, 256>>>(Ah, Al, Bt, qkv, 768);
    attn_kernel<<<ga, Nn>>>(qkv, bulk, col_bw, col_bb, Ah, Al, 1, Nn);
    splitB<<<(GK * 256 + 255) / 256, 256>>>(col_out_w, Bt, 256);
    gemm_mma<<<gp, 256>>>(Ah, Al, Bt, proj, 256);
    ln_kernel<<<ROWS, Cc>>>(x1, proj, col_ln_g, col_ln_b, out, nullptr, nullptr);
}